// round 8
// baseline (speedup 1.0000x reference)
#include <cuda_runtime.h>

// LossGenerator: T=11, H=W=2048. Inputs u=output, f1, each [11,1,2048,2048] f32.
// Output: [phy, bc] f32. Single fused kernel.
// 1 pixel/thread: warp = 32 contiguous columns, uc[11] temporal history
// (11 regs) -> fits 48-reg cap -> 5 CTAs/SM (62.5% occupancy).
// Separable stencil: q = A*(top+bot) + B*mid; conv = qL + qR + B*ca + C*mid.

#define HH 2048
#define WI 2048
static const size_t HWs = (size_t)HH * (size_t)WI;

#define NB_BC   10
#define NB_PHY  16384    // 64 col-segments (32 px) x 256 row-groups (8 rows)
#define NB_TOT  (NB_BC + NB_PHY)

__device__ double   g_phy;
__device__ double   g_bc;
__device__ unsigned g_count;

constexpr double PREFD = 3.5682482323055424;  // 0.1^{-0.5}/Gamma(1.5)
constexpr double WQ[10] = {
    1.0,
    0.41421356237309515,
    0.31783724519578215,
    0.26794919243112270,
    0.23606797749978969,
    0.21342176528338802,
    0.19626156828141264,
    0.18267581368159972,
    0.17157287525380971,
    0.16227766016837933
};

__device__ __forceinline__ void block_reduce_add(double v, double* target, int tid) {
    #pragma unroll
    for (int o = 16; o > 0; o >>= 1)
        v += __shfl_down_sync(0xffffffffu, v, o);
    __shared__ double sr[8];
    int lane = tid & 31, wid = tid >> 5;
    if (lane == 0) sr[wid] = v;
    __syncthreads();
    if (wid == 0) {
        v = (lane < 8) ? sr[lane] : 0.0;
        #pragma unroll
        for (int o = 4; o > 0; o >>= 1)
            v += __shfl_down_sync(0xffffffffu, v, o);
        if (lane == 0) atomicAdd(target, v);
    }
}

__global__ __launch_bounds__(256, 5) void fused_kernel(const float* __restrict__ u,
                                                       const float* __restrict__ f1,
                                                       float* __restrict__ out) {
    const int tid = threadIdx.x;
    const int bid = blockIdx.x;

    if (bid < NB_BC) {
        // ---------------- boundary-condition loss ----------------
        const int it = bid;                      // time slice it+1
        const float* ut = u + (size_t)(it + 1) * HWs;
        const float tval = 0.1f + 0.1f * (float)it;
        const float tt = powf(tval, 1.5f);

        double v = 0.0;
        #pragma unroll
        for (int jb = 0; jb < 8; jb++) {
            const int j = jb * 256 + tid;        // 0..2047
            const float xj = (float)j * (1.0f / 2047.0f);
            const float x1b = tt * sinf(6.2831853071795862f * xj);

            const float l  = ut[(size_t)j * WI];
            const float r  = ut[(size_t)j * WI + (WI - 1)];
            const float tp = ut[j];
            const float bt = ut[(size_t)(HH - 1) * WI + j];

            const float dl = l - x1b, dr = r - x1b, du = tp - x1b, db = bt - x1b;
            v += (double)(dl * dl + dr * dr + du * du + db * db);
        }
        block_reduce_add(v, &g_bc, tid);
    } else {
        // ---------------- physics residual loss ----------------
        const int b    = bid - NB_BC;
        const int lane = tid & 31;
        const int wrp  = tid >> 5;               // 0..7
        const int seg  = b & 63;                 // col segment of 32 px
        const int h    = 1 + (b >> 6) * 8 + wrp; // row, 1..2048 (mask > 2046)
        const int w    = seg * 32 + lane;        // 0..2047

        float acc = 0.0f;

        if (h <= HH - 2) {
            const float A = 0.34520446044393f;
            const float B = 0.309591078922457f;
            const float C = -2.619182157203629f;
            const float KLAP = 0.01f * 4194304.0f;     // kappa / DX^2

            const float fPW[10] = {
                (float)(PREFD * WQ[0]), (float)(PREFD * WQ[1]), (float)(PREFD * WQ[2]),
                (float)(PREFD * WQ[3]), (float)(PREFD * WQ[4]), (float)(PREFD * WQ[5]),
                (float)(PREFD * WQ[6]), (float)(PREFD * WQ[7]), (float)(PREFD * WQ[8]),
                (float)(PREFD * WQ[9])
            };
            const float fPD[10] = {
                0.0f,
                (float)(PREFD * (WQ[0] - WQ[1])), (float)(PREFD * (WQ[1] - WQ[2])),
                (float)(PREFD * (WQ[2] - WQ[3])), (float)(PREFD * (WQ[3] - WQ[4])),
                (float)(PREFD * (WQ[4] - WQ[5])), (float)(PREFD * (WQ[5] - WQ[6])),
                (float)(PREFD * (WQ[6] - WQ[7])), (float)(PREFD * (WQ[7] - WQ[8])),
                (float)(PREFD * (WQ[8] - WQ[9]))
            };
            const float PREFF = (float)PREFD;

            const float msk = (w >= 1 && w <= WI - 2) ? 1.0f : 0.0f;
            // Edge lanes fetch the out-of-warp q column from gmem.
            const bool edge = ((lane == 0) && (w > 0)) ||
                              ((lane == 31) && (w < WI - 1));
            const int  eo   = (lane == 0) ? -1 : 1;

            float uc[11];
            const size_t base = (size_t)(h - 1) * WI + (size_t)w;

            #pragma unroll
            for (int t = 0; t < 11; t++) {
                const float* pt = u + (size_t)t * HWs + base;   // row h-1
                const float* pm = pt + WI;                       // row h
                const float* pb = pm + WI;                       // row h+1
                const float av = *pt;
                const float mv = *pm;
                const float bv = *pb;
                const float fv = *(f1 + (size_t)t * HWs + base + WI);

                float qE = 0.0f;
                if (edge)
                    qE = fmaf(A, pt[eo] + pb[eo], B * pm[eo]);

                const float ca = av + bv;
                const float q  = fmaf(A, ca, B * mv);

                float qL = __shfl_up_sync(0xffffffffu, q, 1);
                float qR = __shfl_down_sync(0xffffffffu, q, 1);
                if (lane == 0)  qL = qE;
                if (lane == 31) qR = qE;

                const float conv = qL + qR + fmaf(B, ca, C * mv);
                float fu = mv - fv - KLAP * conv;
                if (t > 0) {
                    float Dv = PREFF * mv - fPW[t - 1] * uc[0];
                    #pragma unroll
                    for (int k = 1; k < t; k++)
                        Dv -= fPD[t - k] * uc[k];
                    fu += Dv;
                }
                fu *= msk;
                acc = fmaf(fu, fu, acc);
                uc[t] = mv;
            }
        }

        block_reduce_add((double)acc, &g_phy, tid);
    }

    // ---------------- last-block finalize + reset ----------------
    if (tid == 0) {
        __threadfence();
        unsigned prev = atomicAdd(&g_count, 1u);
        if (prev == NB_TOT - 1) {
            out[0] = (float)(2.0 * g_phy / 46047276.0);   // 11*2046*2046
            out[1] = (float)(g_bc / 41943040.0);          // 10*2048*2048
            g_phy = 0.0;
            g_bc  = 0.0;
            g_count = 0u;
            __threadfence();
        }
    }
}

extern "C" void kernel_launch(void* const* d_in, const int* in_sizes, int n_in,
                              void* d_out, int out_size) {
    const float* u  = (const float*)d_in[0];
    const float* f1 = (const float*)d_in[1];
    float* out = (float*)d_out;

    fused_kernel<<<NB_TOT, 256>>>(u, f1, out);
}

// round 10
// speedup vs baseline: 1.5275x; 1.5275x over previous
#include <cuda_runtime.h>
#include <cstdint>

// LossGenerator: T=11, H=W=2048. Inputs u=output, f1, each [11,1,2048,2048] f32.
// Output: [phy, bc] f32. Single fused kernel.
// cp.async 4-stage pipeline: per-t tiles (10 u rows + 8 f1 rows, 64px + halo)
// staged into smem 3 slices ahead of compute -> MLP decoupled from registers.
// R10 fix: full loader coverage (288 cp16 items over 256 threads; tids 0-31
// carry a second f1 chunk). Compute: float2 lanes, q-trick, 2 shuffles/t.

#define HH 2048
#define WI 2048
static const size_t HWs = (size_t)HH * (size_t)WI;

#define NB_BC   10
#define NB_PHY  8192     // 32 col-segments (64 px) x 256 row-groups (8 rows)
#define NB_TOT  (NB_BC + NB_PHY)

#define RS      68       // smem row stride (floats): 64 main + 2 halo + 2 pad
#define SU_ROW  10
#define SF_ROW  8
#define SU_ST   (SU_ROW * RS)   // 680
#define SF_ST   (SF_ROW * RS)   // 544

__device__ double   g_phy;
__device__ double   g_bc;
__device__ unsigned g_count;

constexpr double PREFD = 3.5682482323055424;  // 0.1^{-0.5}/Gamma(1.5)
constexpr double WQ[10] = {
    1.0,
    0.41421356237309515,
    0.31783724519578215,
    0.26794919243112270,
    0.23606797749978969,
    0.21342176528338802,
    0.19626156828141264,
    0.18267581368159972,
    0.17157287525380971,
    0.16227766016837933
};

__device__ __forceinline__ void cp16(uint32_t s, const void* g) {
    asm volatile("cp.async.ca.shared.global [%0], [%1], 16;" :: "r"(s), "l"(g));
}
__device__ __forceinline__ void cp4(uint32_t s, const void* g) {
    asm volatile("cp.async.ca.shared.global [%0], [%1], 4;" :: "r"(s), "l"(g));
}
#define CP_COMMIT() asm volatile("cp.async.commit_group;" ::: "memory")
#define CP_WAIT3()  asm volatile("cp.async.wait_group 3;" ::: "memory")

__device__ __forceinline__ void block_reduce_add(double v, double* target, int tid) {
    #pragma unroll
    for (int o = 16; o > 0; o >>= 1)
        v += __shfl_down_sync(0xffffffffu, v, o);
    __shared__ double sr[8];
    int lane = tid & 31, wid = tid >> 5;
    if (lane == 0) sr[wid] = v;
    __syncthreads();
    if (wid == 0) {
        v = (lane < 8) ? sr[lane] : 0.0;
        #pragma unroll
        for (int o = 4; o > 0; o >>= 1)
            v += __shfl_down_sync(0xffffffffu, v, o);
        if (lane == 0) atomicAdd(target, v);
    }
}

__global__ __launch_bounds__(256, 4) void fused_kernel(const float* __restrict__ u,
                                                       const float* __restrict__ f1,
                                                       float* __restrict__ out) {
    const int tid = threadIdx.x;
    const int bid = blockIdx.x;

    __shared__ float su[4 * SU_ST];   // 10880 B
    __shared__ float sf[4 * SF_ST];   //  8704 B

    if (bid < NB_BC) {
        // ---------------- boundary-condition loss ----------------
        const int it = bid;                      // time slice it+1
        const float* ut = u + (size_t)(it + 1) * HWs;
        const float tval = 0.1f + 0.1f * (float)it;
        const float tt = powf(tval, 1.5f);

        double v = 0.0;
        #pragma unroll
        for (int jb = 0; jb < 8; jb++) {
            const int j = jb * 256 + tid;        // 0..2047
            const float xj = (float)j * (1.0f / 2047.0f);
            const float x1b = tt * sinf(6.2831853071795862f * xj);

            const float l  = ut[(size_t)j * WI];
            const float r  = ut[(size_t)j * WI + (WI - 1)];
            const float tp = ut[j];
            const float bt = ut[(size_t)(HH - 1) * WI + j];

            const float dl = l - x1b, dr = r - x1b, du = tp - x1b, db = bt - x1b;
            v += (double)(dl * dl + dr * dr + du * du + db * db);
        }
        block_reduce_add(v, &g_bc, tid);
    } else {
        // ---------------- physics residual loss ----------------
        const int b     = bid - NB_BC;
        const int lane  = tid & 31;
        const int wrp   = tid >> 5;                 // 0..7 -> output row
        const int seg   = b & 31;                   // 64-px column strip
        const int hgrp  = b >> 5;                   // 0..255
        const int h0    = 1 + hgrp * 8;             // first output row
        const int wbase = seg * 64;
        const int h     = h0 + wrp;                 // this warp's output row
        const int w0    = wbase + lane * 2;         // first of 2 pixels

        const uint32_t su_base = (uint32_t)__cvta_generic_to_shared(su);
        const uint32_t sf_base = (uint32_t)__cvta_generic_to_shared(sf);

        // ---- loader assignment (fixed across t) ----
        // u tile: 10 rows x 16 chunks = 160 cp16 items -> tids 0..159.
        // f tile:  8 rows x 16 chunks = 128 cp16 items -> tids 160..255 take
        //          items 0..95, tids 0..31 take items 96..127 (second copy).
        // halo:   10 rows x 2 sides   =  20 cp4  items -> tids 0..19.
        const bool ldu = (tid < 160);
        size_t gu_off = 0; uint32_t su_off = 0;
        if (ldu) {
            const int ur = tid >> 4, c = tid & 15;
            int hr = h0 - 1 + ur; if (hr > HH - 1) hr = HH - 1;
            gu_off = (size_t)hr * WI + wbase + 4 * c;
            su_off = su_base + (uint32_t)((ur * RS + 4 * c) * 4);
        }
        const int  fitem = (tid >= 160) ? (tid - 160) : (tid < 32 ? 96 + tid : -1);
        const bool ldf = (fitem >= 0);
        size_t gf_off = 0; uint32_t sf_off = 0;
        if (ldf) {
            const int fr = fitem >> 4, c = fitem & 15;
            int hr = h0 + fr; if (hr > HH - 1) hr = HH - 1;
            gf_off = (size_t)hr * WI + wbase + 4 * c;
            sf_off = sf_base + (uint32_t)((fr * RS + 4 * c) * 4);
        }
        const bool ldh = (tid < 20);
        size_t gh_off = 0; uint32_t sh_off = 0;
        if (ldh) {
            const int hrr = tid >> 1, hside = tid & 1;
            int hr = h0 - 1 + hrr; if (hr > HH - 1) hr = HH - 1;
            int col = hside ? (wbase + 64 > WI - 1 ? WI - 1 : wbase + 64)
                            : (wbase - 1 < 0 ? 0 : wbase - 1);
            gh_off = (size_t)hr * WI + col;
            sh_off = su_base + (uint32_t)((hrr * RS + 64 + hside) * 4);
        }

        #define LOAD_STAGE(T, ST)                                                   \
        do {                                                                        \
            if (ldu)                                                                \
                cp16(su_off + (uint32_t)((ST) * SU_ST * 4),                         \
                     u + (size_t)(T) * HWs + gu_off);                               \
            if (ldf)                                                                \
                cp16(sf_off + (uint32_t)((ST) * SF_ST * 4),                         \
                     f1 + (size_t)(T) * HWs + gf_off);                              \
            if (ldh)                                                                \
                cp4(sh_off + (uint32_t)((ST) * SU_ST * 4),                          \
                    u + (size_t)(T) * HWs + gh_off);                                \
            CP_COMMIT();                                                            \
        } while (0)

        LOAD_STAGE(0, 0);
        LOAD_STAGE(1, 1);
        LOAD_STAGE(2, 2);

        const float A = 0.34520446044393f;
        const float B = 0.309591078922457f;
        const float C = -2.619182157203629f;
        const float KLAP = 0.01f * 4194304.0f;     // kappa / DX^2

        const float fPW[10] = {
            (float)(PREFD * WQ[0]), (float)(PREFD * WQ[1]), (float)(PREFD * WQ[2]),
            (float)(PREFD * WQ[3]), (float)(PREFD * WQ[4]), (float)(PREFD * WQ[5]),
            (float)(PREFD * WQ[6]), (float)(PREFD * WQ[7]), (float)(PREFD * WQ[8]),
            (float)(PREFD * WQ[9])
        };
        const float fPD[10] = {
            0.0f,
            (float)(PREFD * (WQ[0] - WQ[1])), (float)(PREFD * (WQ[1] - WQ[2])),
            (float)(PREFD * (WQ[2] - WQ[3])), (float)(PREFD * (WQ[3] - WQ[4])),
            (float)(PREFD * (WQ[4] - WQ[5])), (float)(PREFD * (WQ[5] - WQ[6])),
            (float)(PREFD * (WQ[6] - WQ[7])), (float)(PREFD * (WQ[7] - WQ[8])),
            (float)(PREFD * (WQ[8] - WQ[9]))
        };
        const float PREFF = (float)PREFD;

        const float mskA = (h <= HH - 2) ? 1.0f : 0.0f;
        const float msk0 = mskA * ((w0 == 0)      ? 0.0f : 1.0f);
        const float msk1 = mskA * ((w0 == WI - 2) ? 0.0f : 1.0f);

        float acc = 0.0f;
        float ucm[11][2];

        #pragma unroll
        for (int t = 0; t < 11; t++) {
            const int st = t & 3;
            if (t + 3 <= 10) { LOAD_STAGE(t + 3, (t + 3) & 3); }
            else             { CP_COMMIT(); }
            CP_WAIT3();
            __syncthreads();

            const float* rowT = su + st * SU_ST + wrp * RS;   // u row h-1
            const float* rowM = rowT + RS;                    // u row h
            const float* rowB = rowM + RS;                    // u row h+1
            const float* rowF = sf + st * SF_ST + wrp * RS;   // f1 row h

            const float2 a2 = *(const float2*)(rowT + 2 * lane);
            const float2 m2 = *(const float2*)(rowM + 2 * lane);
            const float2 b2 = *(const float2*)(rowB + 2 * lane);
            const float2 f2 = *(const float2*)(rowF + 2 * lane);

            float qE = 0.0f;
            if (lane == 0 || lane == 31) {
                const int hi = (lane == 0) ? 64 : 65;
                qE = fmaf(A, rowT[hi] + rowB[hi], B * rowM[hi]);
            }

            const float ca0 = a2.x + b2.x, ca1 = a2.y + b2.y;
            const float q0 = fmaf(A, ca0, B * m2.x);
            const float q1 = fmaf(A, ca1, B * m2.y);

            float qL = __shfl_up_sync(0xffffffffu, q1, 1);
            float qR = __shfl_down_sync(0xffffffffu, q0, 1);
            if (lane == 0)  qL = qE;
            if (lane == 31) qR = qE;

            const float qa[4] = { qL, q0, q1, qR };
            const float ca[2] = { ca0, ca1 };
            const float mc[2] = { m2.x, m2.y };
            const float ff[2] = { f2.x, f2.y };
            const float msk[2] = { msk0, msk1 };

            #pragma unroll
            for (int j = 0; j < 2; j++) {
                const float center = mc[j];
                const float conv = qa[j] + qa[j + 2]
                                 + fmaf(B, ca[j], C * center);
                float fu = center - ff[j] - KLAP * conv;
                if (t > 0) {
                    float Dv = PREFF * center - fPW[t - 1] * ucm[0][j];
                    #pragma unroll
                    for (int k = 1; k < t; k++)
                        Dv -= fPD[t - k] * ucm[k][j];
                    fu += Dv;
                }
                fu *= msk[j];
                acc = fmaf(fu, fu, acc);
                ucm[t][j] = center;
            }

            __syncthreads();   // protect stage st before it is re-filled
        }

        block_reduce_add((double)acc, &g_phy, tid);
        #undef LOAD_STAGE
    }

    // ---------------- last-block finalize + reset ----------------
    if (tid == 0) {
        __threadfence();
        unsigned prev = atomicAdd(&g_count, 1u);
        if (prev == NB_TOT - 1) {
            out[0] = (float)(2.0 * g_phy / 46047276.0);   // 11*2046*2046
            out[1] = (float)(g_bc / 41943040.0);          // 10*2048*2048
            g_phy = 0.0;
            g_bc  = 0.0;
            g_count = 0u;
            __threadfence();
        }
    }
}

extern "C" void kernel_launch(void* const* d_in, const int* in_sizes, int n_in,
                              void* d_out, int out_size) {
    const float* u  = (const float*)d_in[0];
    const float* f1 = (const float*)d_in[1];
    float* out = (float*)d_out;

    fused_kernel<<<NB_TOT, 256>>>(u, f1, out);
}